// round 13
// baseline (speedup 1.0000x reference)
#include <cuda_runtime.h>

#define NB   64
#define N    256
#define ND   511          // anti-diagonals
#define BIGV 1e10f

// Diag-major: X[b][d][j] = cell (i=d-j, j).
__device__ float g_Dd[NB * ND * N];
__device__ float g_Wl[NB * ND * N];
__device__ float g_Wd[NB * ND * N];
__device__ float g_Wu[NB * ND * N];
__device__ float g_Ed[NB * ND * N];
__device__ float g_Es[ND * N];

// ---------------------------------------------------------------------------
__global__ void shear_kernel(const float* __restrict__ D) {
    __shared__ float s[32][33];
    const int b = blockIdx.z, i0 = blockIdx.y * 32, j0 = blockIdx.x * 32;
    const int tx = threadIdx.x, ty = threadIdx.y;
    const float* Db = D + (size_t)b * N * N;
    #pragma unroll
    for (int r = ty; r < 32; r += 8) s[r][tx] = Db[(i0 + r) * N + j0 + tx];
    __syncthreads();
    float* out = g_Dd + (size_t)b * ND * N;
    for (int dd = ty; dd < 63; dd += 8) {
        int r = dd - tx;
        if (r >= 0 && r < 32) out[(i0 + j0 + dd) * N + (j0 + tx)] = s[r][tx];
    }
}

__global__ void noop_kernel() {}   // spacers: keep dp_kernel at ncu launch idx 3

// R4-exact softmin cell. zc = __fdiv_rn(-R, 0.01f): the same op every R4
// consumer applied to R (proven bit-identical in R9/R10/R11).
__device__ __forceinline__ void cell_fwd(float zl, float zd, float zu, float th,
                                         float& zc, float& lse_out) {
    const float zmax = fmaxf(fmaxf(zl, zd), zu);
    const float el = expf(__fsub_rn(zl, zmax));
    const float ed = expf(__fsub_rn(zd, zmax));
    const float eu = expf(__fsub_rn(zu, zmax));
    const float ssum = __fadd_rn(__fadd_rn(el, ed), eu);
    const float lse  = __fadd_rn(logf(ssum), zmax);
    const float R    = __fadd_rn(th, __fmul_rn(-0.01f, lse));
    zc = __fdiv_rn(-R, 0.01f);
    lse_out = lse;
}

// ---------------------------------------------------------------------------
// DP: one CTA per batch, 128 threads, thread t owns cols cA=2t, cB=2t+1.
// Cell B feeds purely off own-thread registers (off the barrier chain);
// cell A takes the shfl/boundary edge. One __syncthreads per diagonal.
// All per-cell float ops bit-identical to the R4/R9 passing kernels.
// ---------------------------------------------------------------------------
__global__ __launch_bounds__(128) void dp_kernel() {
    __shared__ float zbuf[4][4];                       // fwd: z of col 64w+63
    __shared__ float ebuf[4][4], wlbuf[4][4], wdbuf[4][4];  // bwd: col 64w

    const int b = blockIdx.x;
    const size_t base = (size_t)b * ND * N;
    const float* __restrict__ Dd = g_Dd + base;
    float* __restrict__ Wl = g_Wl + base;
    float* __restrict__ Wd = g_Wd + base;
    float* __restrict__ Wu = g_Wu + base;
    float* __restrict__ Ed = g_Ed + base;

    const int t = threadIdx.x, w = t >> 5, lane = t & 31;
    const int cA = 2 * t, cB = cA + 1;
    const float ZBIG  = __fdiv_rn(-BIGV, 0.01f);
    const float ZZERO = __fdiv_rn(-0.0f, 0.01f);

    // ================= forward =================
    {
        float zA1 = ZBIG, zA2 = ZBIG, zB1 = ZBIG, zB2 = ZBIG;
        float thA = Dd[cA], thB = Dd[cB];              // 1-deep prefetch
        for (int d = 0; d < ND; ++d) {
            float thAn = 0.f, thBn = 0.f;
            if (d + 1 < ND) {
                thAn = Dd[(size_t)(d + 1) * N + cA];
                thBn = Dd[(size_t)(d + 1) * N + cB];
            }

            const int iA = d - cA, iB = d - cB;
            const bool actA = ((unsigned)iA < 256u), actB = ((unsigned)iB < 256u);

            // ---- cell A (shfl / boundary edge) ----
            float zlA = __shfl_up_sync(0xffffffffu, zB1, 1);   // z(d-1, cA-1)
            float zdA = __shfl_up_sync(0xffffffffu, zB2, 1);   // z(d-2, cA-1)
            if (lane == 0) {
                if (w > 0) { zlA = zbuf[w - 1][(d - 1) & 3];
                             zdA = zbuf[w - 1][(d - 2) & 3]; }
                else       { zlA = ZBIG; zdA = ZBIG; }
            }
            float zuA = zA1;
            if (iA == 0) { zuA = ZBIG; zdA = (cA == 0) ? ZZERO : ZBIG; }

            // ---- cell B (register-only edges) ----
            float zlB = zA1, zdB = zA2, zuB = zB1;
            if (iB == 0) { zuB = ZBIG; zdB = ZBIG; }

            float zcA = ZBIG, lseA = 0.f, zcB = ZBIG, lseB = 0.f;
            if (actA) cell_fwd(zlA, zdA, zuA, thA, zcA, lseA);
            if (actB) cell_fwd(zlB, zdB, zuB, thB, zcB, lseB);

            if (actA) {
                const size_t o = (size_t)d * N + cA;
                Wl[o] = expf(__fsub_rn(zlA, lseA));
                Wd[o] = expf(__fsub_rn(zdA, lseA));
                Wu[o] = expf(__fsub_rn(zuA, lseA));
            }
            if (actB) {
                const size_t o = (size_t)d * N + cB;
                Wl[o] = expf(__fsub_rn(zlB, lseB));
                Wd[o] = expf(__fsub_rn(zdB, lseB));
                Wu[o] = expf(__fsub_rn(zuB, lseB));
                if (lane == 31 && w < 3) zbuf[w][d & 3] = zcB;
            }
            __syncthreads();

            zA2 = zA1; zA1 = actA ? zcA : ZBIG;
            zB2 = zB1; zB1 = actB ? zcB : ZBIG;
            thA = thAn; thB = thBn;
        }
    }
    __syncthreads();

    // ================= backward =================
    {
        float eA1 = 0.f, eA2 = 0.f, eB1 = 0.f, eB2 = 0.f;
        float wlA1 = 0.f, wuA1 = 0.f, wdA1 = 0.f, wdA2 = 0.f;
        float wlB1 = 0.f, wuB1 = 0.f, wdB1 = 0.f, wdB2 = 0.f;
        // W streams at current diag (1-deep prefetch, as R4)
        float wlA0 = Wl[(size_t)(ND - 1) * N + cA], wdA0 = Wd[(size_t)(ND - 1) * N + cA],
              wuA0 = Wu[(size_t)(ND - 1) * N + cA];
        float wlB0 = Wl[(size_t)(ND - 1) * N + cB], wdB0 = Wd[(size_t)(ND - 1) * N + cB],
              wuB0 = Wu[(size_t)(ND - 1) * N + cB];

        for (int d = ND - 1; d >= 0; --d) {
            float wlAn = 0.f, wdAn = 0.f, wuAn = 0.f;
            float wlBn = 0.f, wdBn = 0.f, wuBn = 0.f;
            if (d > 0) {
                wlAn = Wl[(size_t)(d - 1) * N + cA];
                wdAn = Wd[(size_t)(d - 1) * N + cA];
                wuAn = Wu[(size_t)(d - 1) * N + cA];
                wlBn = Wl[(size_t)(d - 1) * N + cB];
                wdBn = Wd[(size_t)(d - 1) * N + cB];
                wuBn = Wu[(size_t)(d - 1) * N + cB];
            }

            const int iA = d - cA, iB = d - cB;
            const bool actA = ((unsigned)iA < 256u), actB = ((unsigned)iB < 256u);

            // ---- cell B neighbor (col cB+1 = next thread's cA): shfl/boundary ----
            float sE1  = __shfl_down_sync(0xffffffffu, eA1, 1);   // E(d+1, cB+1)
            float sE2  = __shfl_down_sync(0xffffffffu, eA2, 1);   // E(d+2, cB+1)
            float sWl1 = __shfl_down_sync(0xffffffffu, wlA1, 1);  // Wl(d+1, cB+1)
            float sWd2 = __shfl_down_sync(0xffffffffu, wdA2, 1);  // Wd(d+2, cB+1)
            if (lane == 31) {
                if (w < 3) {
                    sE1  = ebuf [w + 1][(d + 1) & 3];
                    sE2  = ebuf [w + 1][(d + 2) & 3];
                    sWl1 = wlbuf[w + 1][(d + 1) & 3];
                    sWd2 = wdbuf[w + 1][(d + 2) & 3];
                } else { sE1 = 0.f; sE2 = 0.f; sWl1 = 0.f; sWd2 = 0.f; }
            }

            // ---- cell A: neighbor col cB = own registers ----
            float eA = 0.f;
            if (actA) {
                const bool ilt = (iA < 255);          // cA <= 254 always
                const float t0 = __fmul_rn(wlB1, eB1);
                const float t1 = ilt ? __fmul_rn(wdB2, eB2) : 0.f;
                const float t2 = ilt ? __fmul_rn(wuA1, eA1) : 0.f;
                eA = __fadd_rn(__fadd_rn(t0, t1), t2);
            }

            // ---- cell B ----
            float eB = 0.f;
            if (actB) {
                const bool jlt = (cB < 255);
                const bool ilt = (iB < 255);
                const float t0 = jlt          ? __fmul_rn(sWl1, sE1) : 0.f;
                const float t1 = (jlt && ilt) ? __fmul_rn(sWd2, sE2) : 0.f;
                const float t2 = ilt          ? __fmul_rn(wuB1, eB1) : 0.f;
                eB = __fadd_rn(__fadd_rn(t0, t1), t2);
                if (iB == 255 && cB == 255) eB = 1.0f;
            }

            if (actA) {
                Ed[(size_t)d * N + cA] = eA;
                if (lane == 0 && w > 0) {
                    ebuf [w][d & 3] = eA;
                    wlbuf[w][d & 3] = wlA0;
                    wdbuf[w][d & 3] = wdA0;
                }
            }
            if (actB) Ed[(size_t)d * N + cB] = eB;
            __syncthreads();

            eA2 = eA1; eA1 = actA ? eA : 0.f;
            eB2 = eB1; eB1 = actB ? eB : 0.f;
            wdA2 = wdA1; wdA1 = wdA0; wlA1 = wlA0; wuA1 = wuA0;
            wdB2 = wdB1; wdB1 = wdB0; wlB1 = wlB0; wuB1 = wuB0;
            wlA0 = wlAn; wdA0 = wdAn; wuA0 = wuAn;
            wlB0 = wlBn; wdB0 = wdBn; wuB0 = wuBn;
        }
    }
}

// ---------------------------------------------------------------------------
__global__ void reduce_kernel() {
    const int idx = blockIdx.x * blockDim.x + threadIdx.x;
    float s = 0.0f;
    #pragma unroll 4
    for (int b = 0; b < NB; ++b) s += g_Ed[(size_t)b * ND * N + idx];
    g_Es[idx] = s * (1.0f / NB);
}
__global__ void gather_kernel(float* __restrict__ out) {
    const int idx = blockIdx.x * blockDim.x + threadIdx.x;
    const int i = idx >> 8, j = idx & (N - 1);
    out[idx] = g_Es[(i + j) * N + j];
}

// ---------------------------------------------------------------------------
extern "C" void kernel_launch(void* const* d_in, const int* in_sizes, int n_in,
                              void* d_out, int out_size) {
    const float* D = (const float*)d_in[0];
    float* out = (float*)d_out;

    shear_kernel<<<dim3(8, 8, NB), dim3(32, 8)>>>(D);   // launch 0
    noop_kernel<<<1, 32>>>();                           // launch 1 (spacer)
    noop_kernel<<<1, 32>>>();                           // launch 2 (spacer)
    dp_kernel<<<NB, 128>>>();                           // launch 3  <- ncu target
    reduce_kernel<<<ND, 256>>>();                       // launch 4
    gather_kernel<<<(N * N) / 256, 256>>>(out);         // launch 5
}

// round 14
// speedup vs baseline: 1.1115x; 1.1115x over previous
#include <cuda_runtime.h>

#define NB   64
#define N    256
#define ND   511          // anti-diagonals
#define BIGV 1e10f

// Diag-major: X[b][d][j] = cell (i=d-j, j).
__device__ float g_Dd[NB * ND * N];
__device__ float g_Wl[NB * ND * N];
__device__ float g_Wd[NB * ND * N];
__device__ float g_Wu[NB * ND * N];
__device__ float g_Ed[NB * ND * N];
__device__ float g_Es[ND * N];

// ---------------------------------------------------------------------------
__global__ void shear_kernel(const float* __restrict__ D) {
    __shared__ float s[32][33];
    const int b = blockIdx.z, i0 = blockIdx.y * 32, j0 = blockIdx.x * 32;
    const int tx = threadIdx.x, ty = threadIdx.y;
    const float* Db = D + (size_t)b * N * N;
    #pragma unroll
    for (int r = ty; r < 32; r += 8) s[r][tx] = Db[(i0 + r) * N + j0 + tx];
    __syncthreads();
    float* out = g_Dd + (size_t)b * ND * N;
    for (int dd = ty; dd < 63; dd += 8) {
        int r = dd - tx;
        if (r >= 0 && r < 32) out[(i0 + j0 + dd) * N + (j0 + tx)] = s[r][tx];
    }
}

__global__ void noop_kernel() {}   // spacers: keep dp_kernel at ncu launch idx 3

// ---------------------------------------------------------------------------
// Tiled-wavefront DP. 8 warps/CTA, warp w owns tile-row I=w (rows 32w..32w+31).
// 15 tile-diagonal phases; per phase each active warp runs one 32x32 tile =
// 63 register-resident mini-diagonals (lane = tile column). One CTA barrier
// per phase. All per-cell float ops bit-identical to the R4/R9 kernels; z is
// passed (z = __fdiv_rn(-R, 0.01f), the op R4 consumers applied to R).
// ---------------------------------------------------------------------------
__global__ __launch_bounds__(256) void dp_kernel() {
    __shared__ float sF_edge[8][32];      // fwd: right-edge z carry (same warp)
    __shared__ float sF_bot[2][8][32];    // fwd: bottom-row z export (parity)
    __shared__ float sB_eE [8][32];       // bwd: left-edge E carry (same warp)
    __shared__ float sB_eWl[8][32];
    __shared__ float sB_eWd[8][32];
    __shared__ float sB_top[2][8][32];    // bwd: top-row E export (parity)

    const int b = blockIdx.x;
    const size_t base = (size_t)b * ND * N;
    const float* __restrict__ Dd = g_Dd + base;
    float* __restrict__ Wl = g_Wl + base;
    float* __restrict__ Wd = g_Wd + base;
    float* __restrict__ Wu = g_Wu + base;
    float* __restrict__ Ed = g_Ed + base;

    const int tid = threadIdx.x, w = tid >> 5, lane = tid & 31;
    const float ZBIG  = __fdiv_rn(-BIGV, 0.01f);
    const float ZZERO = __fdiv_rn(-0.0f, 0.01f);
    const unsigned FULL = 0xffffffffu;

    // ================= forward =================
    {
        float cornerCarry = ZBIG;
        for (int p = 0; p < 15; ++p) {
            const int J = p - w;
            if (0 <= J && J < 8) {
                const int i0 = w << 5, j0 = J << 5;
                const int jg = j0 + lane;
                const int dbase = i0 + j0;

                const float topz   = (w == 0) ? ZBIG : sF_bot[(p - 1) & 1][w - 1][lane];
                const float edgeL  = (J == 0) ? ZBIG : sF_edge[w][lane];
                const float corner = (J == 0) ? ((w == 0) ? ZZERO : ZBIG) : cornerCarry;
                cornerCarry = __shfl_sync(FULL, topz, 31);
                const float topzL = __shfl_up_sync(FULL, topz, 1);   // topz[lane-1]

                float z1 = ZBIG, z2 = ZBIG;
                float th0 = Dd[(size_t)(dbase + 0) * N + jg];
                float th1 = Dd[(size_t)(dbase + 1) * N + jg];
                float th2 = Dd[(size_t)(dbase + 2) * N + jg];

                #pragma unroll 3
                for (int t = 0; t < 63; ++t) {
                    float thN = 0.0f;
                    if (t + 3 <= 62) thN = Dd[(size_t)(dbase + t + 3) * N + jg];

                    const int lr = t - lane;
                    const bool act = ((unsigned)lr < 32u);

                    const float eL1  = __shfl_sync(FULL, edgeL, t & 31);
                    const float eL2p = __shfl_sync(FULL, edgeL, (t - 1) & 31);
                    const float eL2  = (t == 0) ? corner : eL2p;

                    float zl = __shfl_up_sync(FULL, z1, 1);
                    float zd = __shfl_up_sync(FULL, z2, 1);
                    if (lane == 0) { zl = eL1; zd = eL2; }
                    float zu = z1;
                    if (lr == 0) { zu = topz; if (lane > 0) zd = topzL; }

                    // --- R4-exact softmin cell ---
                    const float zmax = fmaxf(fmaxf(zl, zd), zu);
                    const float el = expf(__fsub_rn(zl, zmax));
                    const float ed = expf(__fsub_rn(zd, zmax));
                    const float eu = expf(__fsub_rn(zu, zmax));
                    const float ssum = __fadd_rn(__fadd_rn(el, ed), eu);
                    const float lse  = __fadd_rn(logf(ssum), zmax);
                    const float R    = __fadd_rn(th0, __fmul_rn(-0.01f, lse));
                    const float zc   = __fdiv_rn(-R, 0.01f);

                    if (act) {
                        const size_t o = (size_t)(dbase + t) * N + jg;
                        Wl[o] = expf(__fsub_rn(zl, lse));
                        Wd[o] = expf(__fsub_rn(zd, lse));
                        Wu[o] = expf(__fsub_rn(zu, lse));
                        if (lane == 31) sF_edge[w][lr] = zc;
                        if (lr == 31)   sF_bot[p & 1][w][lane] = zc;
                        z2 = z1; z1 = zc;
                    }
                    th0 = th1; th1 = th2; th2 = thN;
                }
            }
            __syncthreads();
        }
    }
    __syncthreads();

    // ================= backward =================
    {
        float cornerECarry = 0.0f;
        for (int q = 0; q < 15; ++q) {
            const int J = 14 - q - w;
            if (0 <= J && J < 8) {
                const int i0 = w << 5, j0 = J << 5;
                const int jg = j0 + lane;
                const int dtop = i0 + j0 + 62;           // global diag at s=0

                const float belowE  = (w == 7) ? 0.0f : sB_top[(q - 1) & 1][w + 1][lane];
                const float edgeE   = (J == 7) ? 0.0f : sB_eE [w][lane];
                const float edgeWl  = (J == 7) ? 0.0f : sB_eWl[w][lane];
                const float edgeWd  = (J == 7) ? 0.0f : sB_eWd[w][lane];
                const float cornerE = (J == 7) ? 0.0f : cornerECarry;
                cornerECarry = __shfl_sync(FULL, belowE, 0);

                float wlI = 0.f, wdI = 0.f, wuI = 0.f, cornerWd = 0.f;
                if (w < 7) {
                    const size_t o32 = (size_t)(i0 + 32 + jg) * N + jg;  // row i0+32
                    wlI = Wl[o32]; wdI = Wd[o32]; wuI = Wu[o32];
                    if (J < 7) cornerWd = Wd[(size_t)(i0 + j0 + 64) * N + (j0 + 32)];
                }

                float e1 = 0.f, e2 = 0.f;
                float wl1 = 0.f, wd1 = 0.f, wu1 = 0.f, wd2 = 0.f;

                // current-cell W pipe (depth 3): a=step s, b=s+1, c=s+2
                float al = Wl[(size_t)(dtop    ) * N + jg];
                float ad = Wd[(size_t)(dtop    ) * N + jg];
                float au = Wu[(size_t)(dtop    ) * N + jg];
                float bl = Wl[(size_t)(dtop - 1) * N + jg];
                float bd = Wd[(size_t)(dtop - 1) * N + jg];
                float bu = Wu[(size_t)(dtop - 1) * N + jg];
                float cl = Wl[(size_t)(dtop - 2) * N + jg];
                float cd = Wd[(size_t)(dtop - 2) * N + jg];
                float cu = Wu[(size_t)(dtop - 2) * N + jg];

                #pragma unroll 3
                for (int s = 0; s < 63; ++s) {
                    float nl = 0.f, nd = 0.f, nu = 0.f;
                    if (s + 3 <= 62) {
                        const size_t oN = (size_t)(dtop - s - 3) * N + jg;
                        nl = Wl[oN]; nd = Wd[oN]; nu = Wu[oN];
                    }
                    const int lr = (62 - s) - lane;
                    const bool act = ((unsigned)lr < 32u);

                    if (lr == 31) { e1 = belowE; wl1 = wlI; wd1 = wdI; wu1 = wuI; }

                    float sE1  = __shfl_down_sync(FULL, e1, 1);
                    float sE2  = __shfl_down_sync(FULL, e2, 1);
                    float sWl1 = __shfl_down_sync(FULL, wl1, 1);
                    float sWd2 = __shfl_down_sync(FULL, wd2, 1);
                    const float eE1  = __shfl_sync(FULL, edgeE,  (31 - s) & 31);
                    const float eW1  = __shfl_sync(FULL, edgeWl, (31 - s) & 31);
                    const float eE2p = __shfl_sync(FULL, edgeE,  (32 - s) & 31);
                    const float eW2p = __shfl_sync(FULL, edgeWd, (32 - s) & 31);
                    if (lane == 31) {
                        sE1  = eE1;
                        sWl1 = eW1;
                        sE2  = (s == 0) ? cornerE  : eE2p;
                        sWd2 = (s == 0) ? cornerWd : eW2p;
                    }

                    if (act) {
                        const int ii = i0 + lr;
                        const bool jlt = (jg < 255), ilt = (ii < 255);
                        const float t0 = jlt          ? __fmul_rn(sWl1, sE1) : 0.f;
                        const float t1 = (jlt && ilt) ? __fmul_rn(sWd2, sE2) : 0.f;
                        const float t2 = ilt          ? __fmul_rn(wu1,  e1)  : 0.f;
                        float e = __fadd_rn(__fadd_rn(t0, t1), t2);
                        if (ii == 255 && jg == 255) e = 1.0f;
                        Ed[(size_t)(dtop - s) * N + jg] = e;
                        if (lane == 0) { sB_eE[w][lr] = e; sB_eWl[w][lr] = al; sB_eWd[w][lr] = ad; }
                        if (lr == 0) sB_top[q & 1][w][lane] = e;
                        e2 = e1; e1 = e;
                        wd2 = wd1; wd1 = ad; wl1 = al; wu1 = au;
                    }
                    al = bl; ad = bd; au = bu;
                    bl = cl; bd = cd; bu = cu;
                    cl = nl; cd = nd; cu = nu;
                }
            }
            __syncthreads();
        }
    }
}

// ---------------------------------------------------------------------------
__global__ void reduce_kernel() {
    const int idx = blockIdx.x * blockDim.x + threadIdx.x;
    float s = 0.0f;
    #pragma unroll 4
    for (int b = 0; b < NB; ++b) s += g_Ed[(size_t)b * ND * N + idx];
    g_Es[idx] = s * (1.0f / NB);
}
__global__ void gather_kernel(float* __restrict__ out) {
    const int idx = blockIdx.x * blockDim.x + threadIdx.x;
    const int i = idx >> 8, j = idx & (N - 1);
    out[idx] = g_Es[(i + j) * N + j];
}

// ---------------------------------------------------------------------------
extern "C" void kernel_launch(void* const* d_in, const int* in_sizes, int n_in,
                              void* d_out, int out_size) {
    const float* D = (const float*)d_in[0];
    float* out = (float*)d_out;

    shear_kernel<<<dim3(8, 8, NB), dim3(32, 8)>>>(D);   // launch 0
    noop_kernel<<<1, 32>>>();                           // launch 1 (spacer)
    noop_kernel<<<1, 32>>>();                           // launch 2 (spacer)
    dp_kernel<<<NB, 256>>>();                           // launch 3  <- ncu target
    reduce_kernel<<<ND, 256>>>();                       // launch 4
    gather_kernel<<<(N * N) / 256, 256>>>(out);         // launch 5
}